// round 9
// baseline (speedup 1.0000x reference)
#include <cuda_runtime.h>
#include <cuda_bf16.h>
#include <mma.h>
#include <math.h>
#include <stdint.h>

#define N_TOK 4096
#define D 128
#define H 8

using namespace nvcuda;

typedef wmma::fragment<wmma::matrix_a, 16, 16, 16, __nv_bfloat16, wmma::row_major> FragA;
typedef wmma::fragment<wmma::matrix_b, 16, 16, 16, __nv_bfloat16, wmma::col_major> FragB;
typedef wmma::fragment<wmma::accumulator, 16, 16, 16, float> FragC;

// ===========================================================================
// Device-global scratch (no allocations allowed)
// ===========================================================================
__device__ __nv_bfloat16 g_x_hi[N_TOK * D],      g_x_lo[N_TOK * D];
__device__ __nv_bfloat16 g_Wt_hi[3 * H * D * D], g_Wt_lo[3 * H * D * D];   // [p][h][e][d]
__device__ __nv_bfloat16 g_WoT_hi[D * H * D],    g_WoT_lo[D * H * D];      // [f][c]
__device__ __nv_bfloat16 g_q_hi[H * N_TOK * D],  g_q_lo[H * N_TOK * D];    // [h][n][d]
__device__ __nv_bfloat16 g_v_hi[H * N_TOK * D],  g_v_lo[H * N_TOK * D];    // [h][n][d]
__device__ __nv_bfloat16 g_kT_hi[H * D * N_TOK], g_kT_lo[H * D * N_TOK];   // [h][e][m]
__device__ __nv_bfloat16 g_att_hi[N_TOK * H * D], g_att_lo[N_TOK * H * D]; // [n][h*D+d]

// ===========================================================================
// Strides / SMEM layouts
// ===========================================================================
#define LDB  136   // bf16 tile stride (elems), 272B rows
#define LDK  72    // K/P tile stride (elems), 144B rows
#define LDP  72
#define LDS_ 68    // fp32 S stride
#define LDS2 132   // fp32 C staging stride (qkv/oproj)
#define NC   64    // attention chunk count (64-wide chunks)

#define OFF_MS   0
#define OFF_LS   512
#define OFF_FAC  1024
#define OFF_RED  1536
#define OFF_BIAS 2560

// qkv layout (128x128 tiles everywhere)
#define OFF_AHI  4096
#define OFF_ALO  (OFF_AHI + 34816)
#define OFF_BHI  (OFF_ALO + 34816)
#define OFF_BLO  (OFF_BHI + 34816)
#define OFF_C    (OFF_BLO + 34816)             // fp32 staging 128 x 132
#define SM_QKV   (OFF_C + 128 * LDS2 * 4)      // 210944

// attn layout
#define AT_V  4096                              // V: 2 planes of 128x136
#define AT_Q  (AT_V + 69632)                    // Q: 2 planes of 64x136
#define AT_K  (AT_Q + 34816)                    // K: 2 planes of 128x72
#define AT_P  (AT_K + 36864)                    // P: 2 planes of 128x72
#define AT_S  (AT_P + 36864)                    // S: fp32 128x68
#define SM_ATTN (AT_S + 34816)                  // 217088

// oproj layout (64-row tiles)
#define OP_A  4096                              // 2 planes of 64x136
#define OP_B  (OP_A + 34816)                    // 2 planes of 128x136
#define OP_C  (OP_B + 69632)                    // fp32 64x132
#define SM_OPROJ (OP_C + 64 * LDS2 * 4)         // 142336

// ===========================================================================
// cp.async helpers (base ISA sm_80+, legal under compute_103)
// ===========================================================================
__device__ __forceinline__ void cp_async16(__nv_bfloat16* dst, const __nv_bfloat16* src) {
    uint32_t d;
    asm("{ .reg .u64 t; cvta.to.shared.u64 t, %1; cvt.u32.u64 %0, t; }" : "=r"(d) : "l"(dst));
    asm volatile("cp.async.cg.shared.global [%0], [%1], 16;" :: "r"(d), "l"(src) : "memory");
}
#define CP_COMMIT() asm volatile("cp.async.commit_group;" ::: "memory")
#define CP_WAIT1()  asm volatile("cp.async.wait_group 1;" ::: "memory")
#define CP_WAIT0()  asm volatile("cp.async.wait_group 0;" ::: "memory")

// ===========================================================================
// GEMM helpers (3-term bf16 split: Ah*Bh + Ah*Bl + Al*Bh)
// ===========================================================================
// 2x2 accumulator, K=128, both operands stride LDB
__device__ __forceinline__ void gemm3_22(FragC acc[2][2],
                                         const __nv_bfloat16* Ahi, const __nv_bfloat16* Alo,
                                         const __nv_bfloat16* Bhi, const __nv_bfloat16* Blo,
                                         int r0, int c0) {
    #pragma unroll
    for (int k = 0; k < 8; k++) {
        FragA ah[2], al[2];
        FragB bh[2], bl[2];
        #pragma unroll
        for (int i = 0; i < 2; i++) {
            wmma::load_matrix_sync(ah[i], Ahi + (r0 + 16 * i) * LDB + 16 * k, LDB);
            wmma::load_matrix_sync(al[i], Alo + (r0 + 16 * i) * LDB + 16 * k, LDB);
        }
        #pragma unroll
        for (int j = 0; j < 2; j++) {
            wmma::load_matrix_sync(bh[j], Bhi + (c0 + 16 * j) * LDB + 16 * k, LDB);
            wmma::load_matrix_sync(bl[j], Blo + (c0 + 16 * j) * LDB + 16 * k, LDB);
        }
        #pragma unroll
        for (int i = 0; i < 2; i++)
            #pragma unroll
            for (int j = 0; j < 2; j++) {
                wmma::mma_sync(acc[i][j], ah[i], bh[j], acc[i][j]);
                wmma::mma_sync(acc[i][j], ah[i], bl[j], acc[i][j]);
                wmma::mma_sync(acc[i][j], al[i], bh[j], acc[i][j]);
            }
    }
}

// 2x4 accumulator, K=64; A stride LDP, B stride LDK  (GEMM2: O += P @ K)
__device__ __forceinline__ void gemm3_o(FragC acc[2][4],
                                        const __nv_bfloat16* Ahi, const __nv_bfloat16* Alo,
                                        const __nv_bfloat16* Bhi, const __nv_bfloat16* Blo,
                                        int r0, int c0) {
    #pragma unroll
    for (int k = 0; k < 4; k++) {
        FragA ah[2], al[2];
        FragB bh[4], bl[4];
        #pragma unroll
        for (int i = 0; i < 2; i++) {
            wmma::load_matrix_sync(ah[i], Ahi + (r0 + 16 * i) * LDP + 16 * k, LDP);
            wmma::load_matrix_sync(al[i], Alo + (r0 + 16 * i) * LDP + 16 * k, LDP);
        }
        #pragma unroll
        for (int j = 0; j < 4; j++) {
            wmma::load_matrix_sync(bh[j], Bhi + (c0 + 16 * j) * LDK + 16 * k, LDK);
            wmma::load_matrix_sync(bl[j], Blo + (c0 + 16 * j) * LDK + 16 * k, LDK);
        }
        #pragma unroll
        for (int i = 0; i < 2; i++)
            #pragma unroll
            for (int j = 0; j < 4; j++) {
                wmma::mma_sync(acc[i][j], ah[i], bh[j], acc[i][j]);
                wmma::mma_sync(acc[i][j], ah[i], bl[j], acc[i][j]);
                wmma::mma_sync(acc[i][j], al[i], bh[j], acc[i][j]);
            }
    }
}

// 2x4 accumulator, K=128, both stride LDB (qkv full tile)
__device__ __forceinline__ void gemm3_24(FragC acc[2][4],
                                         const __nv_bfloat16* Ahi, const __nv_bfloat16* Alo,
                                         const __nv_bfloat16* Bhi, const __nv_bfloat16* Blo,
                                         int r0, int c0) {
    #pragma unroll
    for (int k = 0; k < 8; k++) {
        FragA ah[2], al[2];
        FragB bh[4], bl[4];
        #pragma unroll
        for (int i = 0; i < 2; i++) {
            wmma::load_matrix_sync(ah[i], Ahi + (r0 + 16 * i) * LDB + 16 * k, LDB);
            wmma::load_matrix_sync(al[i], Alo + (r0 + 16 * i) * LDB + 16 * k, LDB);
        }
        #pragma unroll
        for (int j = 0; j < 4; j++) {
            wmma::load_matrix_sync(bh[j], Bhi + (c0 + 16 * j) * LDB + 16 * k, LDB);
            wmma::load_matrix_sync(bl[j], Blo + (c0 + 16 * j) * LDB + 16 * k, LDB);
        }
        #pragma unroll
        for (int i = 0; i < 2; i++)
            #pragma unroll
            for (int j = 0; j < 4; j++) {
                wmma::mma_sync(acc[i][j], ah[i], bh[j], acc[i][j]);
                wmma::mma_sync(acc[i][j], ah[i], bl[j], acc[i][j]);
                wmma::mma_sync(acc[i][j], al[i], bh[j], acc[i][j]);
            }
    }
}

// ===========================================================================
// Tile loaders
// ===========================================================================
// sync: 128 rows x 128 cols bf16 -> [128][LDB]
__device__ __forceinline__ void ld_tile(const __nv_bfloat16* __restrict__ src,
                                        int stride, __nv_bfloat16* __restrict__ dst) {
    int tid = threadIdx.x;
    #pragma unroll
    for (int it = 0; it < 8; it++) {
        int idx = tid + it * 256;
        int row = idx >> 4, c16 = idx & 15;
        *(uint4*)(dst + row * LDB + c16 * 8) =
            *(const uint4*)(src + (size_t)row * stride + c16 * 8);
    }
}
// sync: 64 rows x 128 cols bf16 -> [64][LDB]
__device__ __forceinline__ void ld_tile64(const __nv_bfloat16* __restrict__ src,
                                          int stride, __nv_bfloat16* __restrict__ dst) {
    int tid = threadIdx.x;
    #pragma unroll
    for (int it = 0; it < 4; it++) {
        int idx = tid + it * 256;
        int row = idx >> 4, c16 = idx & 15;
        *(uint4*)(dst + row * LDB + c16 * 8) =
            *(const uint4*)(src + (size_t)row * stride + c16 * 8);
    }
}
// async: 64 rows x 128 cols (Q chunk), src stride D -> [64][LDB]
__device__ __forceinline__ void ldq_async(const __nv_bfloat16* __restrict__ src,
                                          __nv_bfloat16* __restrict__ dst) {
    int tid = threadIdx.x;
    #pragma unroll
    for (int it = 0; it < 4; it++) {
        int idx = tid + it * 256;
        int row = idx >> 4, c16 = idx & 15;
        cp_async16(dst + row * LDB + c16 * 8, src + (size_t)row * D + c16 * 8);
    }
}
// async: 128 rows (d) x 64 cols (m) (K^T chunk), src stride N_TOK -> [128][LDK]
__device__ __forceinline__ void ldk_async(const __nv_bfloat16* __restrict__ src,
                                          __nv_bfloat16* __restrict__ dst) {
    int tid = threadIdx.x;
    #pragma unroll
    for (int it = 0; it < 4; it++) {
        int idx = tid + it * 256;
        int row = idx >> 3, c16 = idx & 7;
        cp_async16(dst + row * LDK + c16 * 8, src + (size_t)row * N_TOK + c16 * 8);
    }
}

__device__ __forceinline__ uint32_t pack_hi(float a, float b, float& la, float& lb) {
    __nv_bfloat162 t = __floats2bfloat162_rn(a, b);
    la = a - __bfloat162float(t.x);
    lb = b - __bfloat162float(t.y);
    return *reinterpret_cast<uint32_t*>(&t);
}
__device__ __forceinline__ uint32_t pack2(float a, float b) {
    __nv_bfloat162 t = __floats2bfloat162_rn(a, b);
    return *reinterpret_cast<uint32_t*>(&t);
}

// ===========================================================================
// Kernel 0: split + transpose prep for x, Wq/Wk/Wv, Wo
// ===========================================================================
__global__ void prep_kernel(const float* __restrict__ x,
                            const float* __restrict__ Wq, const float* __restrict__ Wk,
                            const float* __restrict__ Wv, const float* __restrict__ Wo) {
    int stride = gridDim.x * blockDim.x;
    int t0 = blockIdx.x * blockDim.x + threadIdx.x;
    for (int i = t0; i < N_TOK * D; i += stride) {
        float v = x[i];
        __nv_bfloat16 hi = __float2bfloat16_rn(v);
        g_x_hi[i] = hi;
        g_x_lo[i] = __float2bfloat16_rn(v - __bfloat162float(hi));
    }
    for (int i = t0; i < 3 * H * D * D; i += stride) {
        int p = i >> 17;
        int r = i & 131071;
        int h = r >> 14;
        int d = (r >> 7) & 127;
        int e = r & 127;
        const float* W = (p == 0) ? Wq : (p == 1) ? Wk : Wv;
        float v = W[r];
        int dst = ((p * H + h) * D + e) * D + d;
        __nv_bfloat16 hi = __float2bfloat16_rn(v);
        g_Wt_hi[dst] = hi;
        g_Wt_lo[dst] = __float2bfloat16_rn(v - __bfloat162float(hi));
    }
    for (int i = t0; i < (H * D) * D; i += stride) {
        int c = i >> 7, f = i & 127;
        float v = Wo[i];
        int dst = f * (H * D) + c;
        __nv_bfloat16 hi = __float2bfloat16_rn(v);
        g_WoT_hi[dst] = hi;
        g_WoT_lo[dst] = __float2bfloat16_rn(v - __bfloat162float(hi));
    }
}

// ===========================================================================
// Kernel A: qkv projections (unchanged structure from R7)
// ===========================================================================
__global__ void __launch_bounds__(256, 1)
qkv_tc_kernel(const float* __restrict__ bq, const float* __restrict__ bk,
              const float* __restrict__ bv) {
    extern __shared__ char sm[];
    __nv_bfloat16* Ahi = (__nv_bfloat16*)(sm + OFF_AHI);
    __nv_bfloat16* Alo = (__nv_bfloat16*)(sm + OFF_ALO);
    __nv_bfloat16* Bhi = (__nv_bfloat16*)(sm + OFF_BHI);
    __nv_bfloat16* Blo = (__nv_bfloat16*)(sm + OFF_BLO);
    float* Csm = (float*)(sm + OFF_C);
    float* bias = (float*)(sm + OFF_BIAS);

    int tid = threadIdx.x, wid = tid >> 5;
    int p = blockIdx.y >> 3, h = blockIdx.y & 7;
    int n0 = blockIdx.x * 128;
    int r0 = (wid & 3) * 32, c0 = (wid >> 2) * 64;

    const float* b = (p == 0) ? bq : (p == 1) ? bk : bv;
    if (tid < 128) bias[tid] = b[h * D + tid];

    ld_tile(g_x_hi + (size_t)n0 * D, D, Ahi);
    ld_tile(g_x_lo + (size_t)n0 * D, D, Alo);
    size_t wt = ((size_t)(p * H + h)) * D * D;
    ld_tile(g_Wt_hi + wt, D, Bhi);
    ld_tile(g_Wt_lo + wt, D, Blo);
    __syncthreads();

    FragC acc[2][4];
    #pragma unroll
    for (int i = 0; i < 2; i++)
        #pragma unroll
        for (int j = 0; j < 4; j++) wmma::fill_fragment(acc[i][j], 0.f);

    gemm3_24(acc, Ahi, Alo, Bhi, Blo, r0, c0);

    #pragma unroll
    for (int i = 0; i < 2; i++)
        #pragma unroll
        for (int j = 0; j < 4; j++)
            wmma::store_matrix_sync(&Csm[(r0 + 16 * i) * LDS2 + c0 + 16 * j],
                                    acc[i][j], LDS2, wmma::mem_row_major);
    __syncthreads();

    int row = tid & 127, half = tid >> 7;
    if (p == 1) {
        #pragma unroll
        for (int c = 0; c < 64; c++) {
            int col = half * 64 + c;
            float v = Csm[row * LDS2 + col] + bias[col];
            __nv_bfloat16 hi = __float2bfloat16_rn(v);
            size_t off = ((size_t)(h * D + col)) * N_TOK + n0 + row;
            g_kT_hi[off] = hi;
            g_kT_lo[off] = __float2bfloat16_rn(v - __bfloat162float(hi));
        }
    } else {
        __nv_bfloat16* oh = ((p == 0) ? g_q_hi : g_v_hi) +
                            ((size_t)h * N_TOK + n0 + row) * D + half * 64;
        __nv_bfloat16* ol = ((p == 0) ? g_q_lo : g_v_lo) +
                            ((size_t)h * N_TOK + n0 + row) * D + half * 64;
        #pragma unroll
        for (int g = 0; g < 8; g++) {
            uint32_t hw[4], lw[4];
            #pragma unroll
            for (int q = 0; q < 4; q++) {
                int col = half * 64 + g * 8 + 2 * q;
                float a  = Csm[row * LDS2 + col]     + bias[col];
                float d2 = Csm[row * LDS2 + col + 1] + bias[col + 1];
                float la, lb;
                hw[q] = pack_hi(a, d2, la, lb);
                lw[q] = pack2(la, lb);
            }
            ((uint4*)oh)[g] = make_uint4(hw[0], hw[1], hw[2], hw[3]);
            ((uint4*)ol)[g] = make_uint4(lw[0], lw[1], lw[2], lw[3]);
        }
    }
}

// ===========================================================================
// Kernel B: flash attention, 64-col chunks + cp.async pipeline.
// grid (32, H), block 256.
// ===========================================================================
__global__ void __launch_bounds__(256, 1) attn_tc_kernel() {
    extern __shared__ char sm[];
    __nv_bfloat16* Vhi = (__nv_bfloat16*)(sm + AT_V);
    __nv_bfloat16* Vlo = Vhi + 128 * LDB;
    __nv_bfloat16* Qhi = (__nv_bfloat16*)(sm + AT_Q);
    __nv_bfloat16* Qlo = Qhi + 64 * LDB;
    __nv_bfloat16* Khi = (__nv_bfloat16*)(sm + AT_K);
    __nv_bfloat16* Klo = Khi + 128 * LDK;
    __nv_bfloat16* Phi = (__nv_bfloat16*)(sm + AT_P);
    __nv_bfloat16* Plo = Phi + 128 * LDP;
    float* Ssm = (float*)(sm + AT_S);
    float* m_s = (float*)(sm + OFF_MS);
    float* l_s = (float*)(sm + OFF_LS);
    float* fac = (float*)(sm + OFF_FAC);
    float* red = (float*)(sm + OFF_RED);

    int tid = threadIdx.x, wid = tid >> 5;
    int h = blockIdx.y, n0 = blockIdx.x * 128;
    int r0  = (wid & 3) * 32;          // output rows of this warp
    int c0s = (wid >> 2) * 32;         // S cols (GEMM1)
    int c0b = (wid >> 2) * 64;         // O cols (GEMM2)
    int row = tid & 127, half = tid >> 7;

    if (tid < 128) { m_s[tid] = -INFINITY; l_s[tid] = 0.f; }

    const __nv_bfloat16* qbase_hi = g_q_hi + (size_t)h * N_TOK * D;
    const __nv_bfloat16* qbase_lo = g_q_lo + (size_t)h * N_TOK * D;
    const __nv_bfloat16* kbase_hi = g_kT_hi + (size_t)h * D * N_TOK;
    const __nv_bfloat16* kbase_lo = g_kT_lo + (size_t)h * D * N_TOK;

    // prologue: V sync, Q(0)/K(0) async
    ld_tile(g_v_hi + ((size_t)h * N_TOK + n0) * D, D, Vhi);
    ld_tile(g_v_lo + ((size_t)h * N_TOK + n0) * D, D, Vlo);
    ldq_async(qbase_hi, Qhi);
    ldq_async(qbase_lo, Qlo);
    CP_COMMIT();                                   // group Q(0)
    ldk_async(kbase_hi, Khi);
    ldk_async(kbase_lo, Klo);
    CP_COMMIT();                                   // group K(0)

    FragC o[2][4];
    #pragma unroll
    for (int i = 0; i < 2; i++)
        #pragma unroll
        for (int j = 0; j < 4; j++) wmma::fill_fragment(o[i][j], 0.f);

    for (int jt = 0; jt < NC; jt++) {
        // ---- wait Q(jt) (K(jt) may still be in flight) ----
        CP_WAIT1();
        __syncthreads();

        // ---- GEMM1: S[128x64] = V @ Q^T ----
        FragC s[2][2];
        #pragma unroll
        for (int i = 0; i < 2; i++)
            #pragma unroll
            for (int j = 0; j < 2; j++) wmma::fill_fragment(s[i][j], 0.f);
        gemm3_22(s, Vhi, Vlo, Qhi, Qlo, r0, c0s);
        __syncthreads();                            // all warps done reading Q

        // ---- prefetch Q(jt+1) (overlaps softmax + GEMM2) ----
        if (jt + 1 < NC) {
            ldq_async(qbase_hi + (size_t)(jt + 1) * 64 * D, Qhi);
            ldq_async(qbase_lo + (size_t)(jt + 1) * 64 * D, Qlo);
            CP_COMMIT();
        }

        #pragma unroll
        for (int i = 0; i < 2; i++)
            #pragma unroll
            for (int j = 0; j < 2; j++)
                wmma::store_matrix_sync(&Ssm[(r0 + 16 * i) * LDS_ + c0s + 16 * j],
                                        s[i][j], LDS_, wmma::mem_row_major);
        __syncthreads();

        // ---- softmax pass 1: row max (thread: row, 32 cols) ----
        {
            float lmax = -INFINITY;
            const float4* sp = (const float4*)&Ssm[row * LDS_ + half * 32];
            #pragma unroll
            for (int q4 = 0; q4 < 8; q4++) {
                float4 v4 = sp[q4];
                lmax = fmaxf(lmax, fmaxf(fmaxf(v4.x, v4.y), fmaxf(v4.z, v4.w)));
            }
            red[tid] = lmax;
        }
        __syncthreads();
        if (tid < 128) {
            float mo = m_s[tid];
            float mn = fmaxf(mo, fmaxf(red[tid], red[tid + 128]));
            m_s[tid] = mn;
            fac[tid] = __expf(mo - mn);
        }
        __syncthreads();

        // ---- softmax pass 2: exp, row sums, pack P hi/lo ----
        {
            float mn = m_s[row];
            float lsum = 0.f;
            __nv_bfloat16* ph = Phi + row * LDP + half * 32;
            __nv_bfloat16* pl = Plo + row * LDP + half * 32;
            #pragma unroll
            for (int g = 0; g < 4; g++) {
                uint32_t hw[4], lw[4];
                #pragma unroll
                for (int q = 0; q < 4; q++) {
                    int col = half * 32 + g * 8 + 2 * q;
                    float a  = __expf(Ssm[row * LDS_ + col]     - mn);
                    float b2 = __expf(Ssm[row * LDS_ + col + 1] - mn);
                    lsum += a + b2;
                    float la, lb;
                    hw[q] = pack_hi(a, b2, la, lb);
                    lw[q] = pack2(la, lb);
                }
                ((uint4*)ph)[g] = make_uint4(hw[0], hw[1], hw[2], hw[3]);
                ((uint4*)pl)[g] = make_uint4(lw[0], lw[1], lw[2], lw[3]);
            }
            red[tid] = lsum;
        }
        __syncthreads();
        if (tid < 128) l_s[tid] = l_s[tid] * fac[tid] + red[tid] + red[tid + 128];

        // ---- rescale O only when some row max changed (rare): safe 2-pass ----
        int need = __syncthreads_or(tid < 128 && jt > 0 && fac[tid] != 1.0f);
        if (need && jt > 0) {
            #pragma unroll
            for (int pass = 0; pass < 2; pass++) {
                if ((wid >> 2) == pass) {
                    #pragma unroll
                    for (int i = 0; i < 2; i++)
                        #pragma unroll
                        for (int j = 0; j < 4; j++)
                            wmma::store_matrix_sync(&Ssm[(r0 + 16 * i) * LDS_ + 16 * j],
                                                    o[i][j], LDS_, wmma::mem_row_major);
                }
                __syncthreads();
                {
                    float f = fac[row];
                    float4* sp = (float4*)&Ssm[row * LDS_ + half * 32];
                    #pragma unroll
                    for (int q4 = 0; q4 < 8; q4++) {
                        float4 v4 = sp[q4];
                        v4.x *= f; v4.y *= f; v4.z *= f; v4.w *= f;
                        sp[q4] = v4;
                    }
                }
                __syncthreads();
                if ((wid >> 2) == pass) {
                    #pragma unroll
                    for (int i = 0; i < 2; i++)
                        #pragma unroll
                        for (int j = 0; j < 4; j++)
                            wmma::load_matrix_sync(o[i][j],
                                                   &Ssm[(r0 + 16 * i) * LDS_ + 16 * j],
                                                   LDS_, wmma::mem_row_major);
                }
                __syncthreads();
            }
        }

        // ---- wait K(jt), then GEMM2: O += P @ K ----
        if (jt + 1 < NC) { CP_WAIT1(); } else { CP_WAIT0(); }
        __syncthreads();
        gemm3_o(o, Phi, Plo, Khi, Klo, r0, c0b);
        __syncthreads();                            // all warps done reading K/P

        // ---- prefetch K(jt+1) (overlaps next GEMM1) ----
        if (jt + 1 < NC) {
            ldk_async(kbase_hi + (size_t)(jt + 1) * 64, Khi);
            ldk_async(kbase_lo + (size_t)(jt + 1) * 64, Klo);
            CP_COMMIT();
        }
    }

    // ---- epilogue: 2-pass O -> SMEM -> normalize/split -> g_att ----
    #pragma unroll
    for (int pass = 0; pass < 2; pass++) {
        if ((wid >> 2) == pass) {
            #pragma unroll
            for (int i = 0; i < 2; i++)
                #pragma unroll
                for (int j = 0; j < 4; j++)
                    wmma::store_matrix_sync(&Ssm[(r0 + 16 * i) * LDS_ + 16 * j],
                                            o[i][j], LDS_, wmma::mem_row_major);
        }
        __syncthreads();
        {
            float inv = 1.f / l_s[row];
            int cbase = pass * 64 + half * 32;
            __nv_bfloat16* oh = g_att_hi + (size_t)(n0 + row) * (H * D) + h * D + cbase;
            __nv_bfloat16* ol = g_att_lo + (size_t)(n0 + row) * (H * D) + h * D + cbase;
            #pragma unroll
            for (int g = 0; g < 4; g++) {
                uint32_t hw[4], lw[4];
                #pragma unroll
                for (int q = 0; q < 4; q++) {
                    int col = half * 32 + g * 8 + 2 * q;
                    float a  = Ssm[row * LDS_ + col]     * inv;
                    float b2 = Ssm[row * LDS_ + col + 1] * inv;
                    float la, lb;
                    hw[q] = pack_hi(a, b2, la, lb);
                    lw[q] = pack2(la, lb);
                }
                ((uint4*)oh)[g] = make_uint4(hw[0], hw[1], hw[2], hw[3]);
                ((uint4*)ol)[g] = make_uint4(lw[0], lw[1], lw[2], lw[3]);
            }
        }
        __syncthreads();
    }
}

// ===========================================================================
// Kernel C: out[n][f] = att[n][:1024] @ WoT^T + bo.  grid 64 (64-row tiles).
// ===========================================================================
__global__ void __launch_bounds__(256, 1)
oproj_tc_kernel(const float* __restrict__ bo, float* __restrict__ out) {
    extern __shared__ char sm[];
    __nv_bfloat16* Ahi = (__nv_bfloat16*)(sm + OP_A);
    __nv_bfloat16* Alo = Ahi + 64 * LDB;
    __nv_bfloat16* Bhi = (__nv_bfloat16*)(sm + OP_B);
    __nv_bfloat16* Blo = Bhi + 128 * LDB;
    float* Csm = (float*)(sm + OP_C);
    float* bias = (float*)(sm + OFF_BIAS);

    int tid = threadIdx.x, wid = tid >> 5;
    int n0 = blockIdx.x * 64;
    int r0 = (wid & 1) * 32, c0 = (wid >> 1) * 32;
    if (tid < 128) bias[tid] = bo[tid];

    FragC acc[2][2];
    #pragma unroll
    for (int i = 0; i < 2; i++)
        #pragma unroll
        for (int j = 0; j < 2; j++) wmma::fill_fragment(acc[i][j], 0.f);

    for (int kt = 0; kt < 8; kt++) {
        ld_tile64(g_att_hi + (size_t)n0 * (H * D) + kt * 128, H * D, Ahi);
        ld_tile64(g_att_lo + (size_t)n0 * (H * D) + kt * 128, H * D, Alo);
        ld_tile(g_WoT_hi + kt * 128, H * D, Bhi);
        ld_tile(g_WoT_lo + kt * 128, H * D, Blo);
        __syncthreads();
        gemm3_22(acc, Ahi, Alo, Bhi, Blo, r0, c0);
        __syncthreads();
    }

    #pragma unroll
    for (int i = 0; i < 2; i++)
        #pragma unroll
        for (int j = 0; j < 2; j++)
            wmma::store_matrix_sync(&Csm[(r0 + 16 * i) * LDS2 + c0 + 16 * j],
                                    acc[i][j], LDS2, wmma::mem_row_major);
    __syncthreads();

    int row = tid >> 2, cq = tid & 3;
    float* op = out + (size_t)(n0 + row) * D + cq * 32;
    #pragma unroll
    for (int q4 = 0; q4 < 8; q4++) {
        int col = cq * 32 + q4 * 4;
        float4 v4 = *(const float4*)&Csm[row * LDS2 + col];
        v4.x += bias[col];     v4.y += bias[col + 1];
        v4.z += bias[col + 2]; v4.w += bias[col + 3];
        ((float4*)op)[q4] = v4;
    }
}

// ===========================================================================
extern "C" void kernel_launch(void* const* d_in, const int* in_sizes, int n_in,
                              void* d_out, int out_size) {
    const float* x  = (const float*)d_in[0];
    const float* Wq = (const float*)d_in[1];
    const float* bq = (const float*)d_in[2];
    const float* Wk = (const float*)d_in[3];
    const float* bk = (const float*)d_in[4];
    const float* Wv = (const float*)d_in[5];
    const float* bv = (const float*)d_in[6];
    const float* Wo = (const float*)d_in[7];
    const float* bo = (const float*)d_in[8];
    float* out = (float*)d_out;

    cudaFuncSetAttribute(qkv_tc_kernel,   cudaFuncAttributeMaxDynamicSharedMemorySize, SM_QKV);
    cudaFuncSetAttribute(attn_tc_kernel,  cudaFuncAttributeMaxDynamicSharedMemorySize, SM_ATTN);
    cudaFuncSetAttribute(oproj_tc_kernel, cudaFuncAttributeMaxDynamicSharedMemorySize, SM_OPROJ);

    prep_kernel<<<256, 256>>>(x, Wq, Wk, Wv, Wo);
    qkv_tc_kernel<<<dim3(32, 24), 256, SM_QKV>>>(bq, bk, bv);
    attn_tc_kernel<<<dim3(32, H), 256, SM_ATTN>>>();
    oproj_tc_kernel<<<64, 256, SM_OPROJ>>>(bo, out);
}

// round 10
// speedup vs baseline: 1.6381x; 1.6381x over previous
#include <cuda_runtime.h>
#include <cuda_bf16.h>
#include <mma.h>
#include <math.h>
#include <stdint.h>

#define N_TOK 4096
#define D 128
#define H 8

using namespace nvcuda;

typedef wmma::fragment<wmma::matrix_a, 16, 16, 16, __nv_bfloat16, wmma::row_major> FragA;
typedef wmma::fragment<wmma::matrix_b, 16, 16, 16, __nv_bfloat16, wmma::col_major> FragB;
typedef wmma::fragment<wmma::accumulator, 16, 16, 16, float> FragC;

// ===========================================================================
// Device-global scratch (no allocations allowed)
// ===========================================================================
__device__ __nv_bfloat16 g_x_hi[N_TOK * D],      g_x_lo[N_TOK * D];
__device__ __nv_bfloat16 g_Wt_hi[3 * H * D * D], g_Wt_lo[3 * H * D * D];   // [p][h][e][d]
__device__ __nv_bfloat16 g_WoT_hi[D * H * D],    g_WoT_lo[D * H * D];      // [f][c]
__device__ __nv_bfloat16 g_q_hi[H * N_TOK * D],  g_q_lo[H * N_TOK * D];    // [h][n][d]
__device__ __nv_bfloat16 g_v_hi[H * N_TOK * D],  g_v_lo[H * N_TOK * D];    // [h][n][d]
__device__ __nv_bfloat16 g_kT_hi[H * D * N_TOK], g_kT_lo[H * D * N_TOK];   // [h][e][m]
__device__ __nv_bfloat16 g_att_hi[N_TOK * H * D], g_att_lo[N_TOK * H * D]; // [n][h*D+d]

// ===========================================================================
// Strides / SMEM layouts
// ===========================================================================
#define LDB  136   // bf16 tile stride (elems) for wmma kernels
#define LDS2 132   // fp32 staging stride (qkv/oproj)
#define LDQ  136   // attn Q plane stride (elems); 272B rows -> conflict-free ldmatrix
#define LDKT 72    // attn K^T plane stride (elems); 144B rows -> conflict-free
#define NC   64    // attention chunks (64 wide)

#define OFF_BIAS 2560

// qkv layout
#define OFF_AHI  4096
#define OFF_ALO  (OFF_AHI + 34816)
#define OFF_BHI  (OFF_ALO + 34816)
#define OFF_BLO  (OFF_BHI + 34816)
#define OFF_C    (OFF_BLO + 34816)
#define SM_QKV   (OFF_C + 128 * LDS2 * 4)

// attn layout: Q double buffer then K^T double buffer. V staged over Qbuf0.
#define AQ0 0
#define AQ1 34816
#define AK0 69632
#define AK1 106496
#define QPL 17408          // bytes per Q plane (64*136*2)
#define KPL 18432          // bytes per K plane (128*72*2)
#define SM_ATTN 143360

// oproj layout (64-row tiles)
#define OP_A  4096
#define OP_B  (OP_A + 34816)
#define OP_C  (OP_B + 69632)
#define SM_OPROJ (OP_C + 64 * LDS2 * 4)

// ===========================================================================
// cp.async + ldmatrix + mma helpers (all base ISA)
// ===========================================================================
__device__ __forceinline__ uint32_t smem_u32(const void* p) {
    uint32_t a;
    asm("{ .reg .u64 t; cvta.to.shared.u64 t, %1; cvt.u32.u64 %0, t; }" : "=r"(a) : "l"(p));
    return a;
}
__device__ __forceinline__ void cp_async16(__nv_bfloat16* dst, const __nv_bfloat16* src) {
    uint32_t d;
    asm("{ .reg .u64 t; cvta.to.shared.u64 t, %1; cvt.u32.u64 %0, t; }" : "=r"(d) : "l"(dst));
    asm volatile("cp.async.cg.shared.global [%0], [%1], 16;" :: "r"(d), "l"(src) : "memory");
}
__device__ __forceinline__ void cp_async16_u(uint32_t dst, const __nv_bfloat16* src) {
    asm volatile("cp.async.cg.shared.global [%0], [%1], 16;" :: "r"(dst), "l"(src) : "memory");
}
#define CP_COMMIT() asm volatile("cp.async.commit_group;" ::: "memory")
#define CP_WAIT0()  asm volatile("cp.async.wait_group 0;" ::: "memory")

#define LDMX4(r, p) \
    asm volatile("ldmatrix.sync.aligned.m8n8.x4.shared.b16 {%0,%1,%2,%3}, [%4];" \
        : "=r"((r)[0]), "=r"((r)[1]), "=r"((r)[2]), "=r"((r)[3]) : "r"(p))

#define MMA16816(d, a, b0, b1) \
    asm volatile("mma.sync.aligned.m16n8k16.row.col.f32.bf16.bf16.f32 " \
        "{%0,%1,%2,%3}, {%4,%5,%6,%7}, {%8,%9}, {%0,%1,%2,%3};" \
        : "+f"((d)[0]), "+f"((d)[1]), "+f"((d)[2]), "+f"((d)[3]) \
        : "r"((a)[0]), "r"((a)[1]), "r"((a)[2]), "r"((a)[3]), "r"(b0), "r"(b1))

__device__ __forceinline__ uint32_t pack_hi(float a, float b, float& la, float& lb) {
    __nv_bfloat162 t = __floats2bfloat162_rn(a, b);
    la = a - __bfloat162float(t.x);
    lb = b - __bfloat162float(t.y);
    return *reinterpret_cast<uint32_t*>(&t);
}
__device__ __forceinline__ uint32_t pack2(float a, float b) {
    __nv_bfloat162 t = __floats2bfloat162_rn(a, b);
    return *reinterpret_cast<uint32_t*>(&t);
}

// ===========================================================================
// WMMA helpers for qkv/oproj (3-term bf16 split)
// ===========================================================================
__device__ __forceinline__ void gemm3_22(FragC acc[2][2],
                                         const __nv_bfloat16* Ahi, const __nv_bfloat16* Alo,
                                         const __nv_bfloat16* Bhi, const __nv_bfloat16* Blo,
                                         int r0, int c0) {
    #pragma unroll
    for (int k = 0; k < 8; k++) {
        FragA ah[2], al[2];
        FragB bh[2], bl[2];
        #pragma unroll
        for (int i = 0; i < 2; i++) {
            wmma::load_matrix_sync(ah[i], Ahi + (r0 + 16 * i) * LDB + 16 * k, LDB);
            wmma::load_matrix_sync(al[i], Alo + (r0 + 16 * i) * LDB + 16 * k, LDB);
        }
        #pragma unroll
        for (int j = 0; j < 2; j++) {
            wmma::load_matrix_sync(bh[j], Bhi + (c0 + 16 * j) * LDB + 16 * k, LDB);
            wmma::load_matrix_sync(bl[j], Blo + (c0 + 16 * j) * LDB + 16 * k, LDB);
        }
        #pragma unroll
        for (int i = 0; i < 2; i++)
            #pragma unroll
            for (int j = 0; j < 2; j++) {
                wmma::mma_sync(acc[i][j], ah[i], bh[j], acc[i][j]);
                wmma::mma_sync(acc[i][j], ah[i], bl[j], acc[i][j]);
                wmma::mma_sync(acc[i][j], al[i], bh[j], acc[i][j]);
            }
    }
}
__device__ __forceinline__ void gemm3_24(FragC acc[2][4],
                                         const __nv_bfloat16* Ahi, const __nv_bfloat16* Alo,
                                         const __nv_bfloat16* Bhi, const __nv_bfloat16* Blo,
                                         int r0, int c0) {
    #pragma unroll
    for (int k = 0; k < 8; k++) {
        FragA ah[2], al[2];
        FragB bh[4], bl[4];
        #pragma unroll
        for (int i = 0; i < 2; i++) {
            wmma::load_matrix_sync(ah[i], Ahi + (r0 + 16 * i) * LDB + 16 * k, LDB);
            wmma::load_matrix_sync(al[i], Alo + (r0 + 16 * i) * LDB + 16 * k, LDB);
        }
        #pragma unroll
        for (int j = 0; j < 4; j++) {
            wmma::load_matrix_sync(bh[j], Bhi + (c0 + 16 * j) * LDB + 16 * k, LDB);
            wmma::load_matrix_sync(bl[j], Blo + (c0 + 16 * j) * LDB + 16 * k, LDB);
        }
        #pragma unroll
        for (int i = 0; i < 2; i++)
            #pragma unroll
            for (int j = 0; j < 4; j++) {
                wmma::mma_sync(acc[i][j], ah[i], bh[j], acc[i][j]);
                wmma::mma_sync(acc[i][j], ah[i], bl[j], acc[i][j]);
                wmma::mma_sync(acc[i][j], al[i], bh[j], acc[i][j]);
            }
    }
}
__device__ __forceinline__ void ld_tile(const __nv_bfloat16* __restrict__ src,
                                        int stride, __nv_bfloat16* __restrict__ dst) {
    int tid = threadIdx.x;
    #pragma unroll
    for (int it = 0; it < 8; it++) {
        int idx = tid + it * 256;
        int row = idx >> 4, c16 = idx & 15;
        *(uint4*)(dst + row * LDB + c16 * 8) =
            *(const uint4*)(src + (size_t)row * stride + c16 * 8);
    }
}
__device__ __forceinline__ void ld_tile64(const __nv_bfloat16* __restrict__ src,
                                          int stride, __nv_bfloat16* __restrict__ dst) {
    int tid = threadIdx.x;
    #pragma unroll
    for (int it = 0; it < 4; it++) {
        int idx = tid + it * 256;
        int row = idx >> 4, c16 = idx & 15;
        *(uint4*)(dst + row * LDB + c16 * 8) =
            *(const uint4*)(src + (size_t)row * stride + c16 * 8);
    }
}

// ===========================================================================
// Kernel 0: split + transpose prep
// ===========================================================================
__global__ void prep_kernel(const float* __restrict__ x,
                            const float* __restrict__ Wq, const float* __restrict__ Wk,
                            const float* __restrict__ Wv, const float* __restrict__ Wo) {
    int stride = gridDim.x * blockDim.x;
    int t0 = blockIdx.x * blockDim.x + threadIdx.x;
    for (int i = t0; i < N_TOK * D; i += stride) {
        float v = x[i];
        __nv_bfloat16 hi = __float2bfloat16_rn(v);
        g_x_hi[i] = hi;
        g_x_lo[i] = __float2bfloat16_rn(v - __bfloat162float(hi));
    }
    for (int i = t0; i < 3 * H * D * D; i += stride) {
        int p = i >> 17;
        int r = i & 131071;
        int h = r >> 14;
        int d = (r >> 7) & 127;
        int e = r & 127;
        const float* W = (p == 0) ? Wq : (p == 1) ? Wk : Wv;
        float v = W[r];
        int dst = ((p * H + h) * D + e) * D + d;
        __nv_bfloat16 hi = __float2bfloat16_rn(v);
        g_Wt_hi[dst] = hi;
        g_Wt_lo[dst] = __float2bfloat16_rn(v - __bfloat162float(hi));
    }
    for (int i = t0; i < (H * D) * D; i += stride) {
        int c = i >> 7, f = i & 127;
        float v = Wo[i];
        int dst = f * (H * D) + c;
        __nv_bfloat16 hi = __float2bfloat16_rn(v);
        g_WoT_hi[dst] = hi;
        g_WoT_lo[dst] = __float2bfloat16_rn(v - __bfloat162float(hi));
    }
}

// ===========================================================================
// Kernel A: qkv projections (R7 structure, known good)
// ===========================================================================
__global__ void __launch_bounds__(256, 1)
qkv_tc_kernel(const float* __restrict__ bq, const float* __restrict__ bk,
              const float* __restrict__ bv) {
    extern __shared__ char sm[];
    __nv_bfloat16* Ahi = (__nv_bfloat16*)(sm + OFF_AHI);
    __nv_bfloat16* Alo = (__nv_bfloat16*)(sm + OFF_ALO);
    __nv_bfloat16* Bhi = (__nv_bfloat16*)(sm + OFF_BHI);
    __nv_bfloat16* Blo = (__nv_bfloat16*)(sm + OFF_BLO);
    float* Csm = (float*)(sm + OFF_C);
    float* bias = (float*)(sm + OFF_BIAS);

    int tid = threadIdx.x, wid = tid >> 5;
    int p = blockIdx.y >> 3, h = blockIdx.y & 7;
    int n0 = blockIdx.x * 128;
    int r0 = (wid & 3) * 32, c0 = (wid >> 2) * 64;

    const float* b = (p == 0) ? bq : (p == 1) ? bk : bv;
    if (tid < 128) bias[tid] = b[h * D + tid];

    ld_tile(g_x_hi + (size_t)n0 * D, D, Ahi);
    ld_tile(g_x_lo + (size_t)n0 * D, D, Alo);
    size_t wt = ((size_t)(p * H + h)) * D * D;
    ld_tile(g_Wt_hi + wt, D, Bhi);
    ld_tile(g_Wt_lo + wt, D, Blo);
    __syncthreads();

    FragC acc[2][4];
    #pragma unroll
    for (int i = 0; i < 2; i++)
        #pragma unroll
        for (int j = 0; j < 4; j++) wmma::fill_fragment(acc[i][j], 0.f);

    gemm3_24(acc, Ahi, Alo, Bhi, Blo, r0, c0);

    #pragma unroll
    for (int i = 0; i < 2; i++)
        #pragma unroll
        for (int j = 0; j < 4; j++)
            wmma::store_matrix_sync(&Csm[(r0 + 16 * i) * LDS2 + c0 + 16 * j],
                                    acc[i][j], LDS2, wmma::mem_row_major);
    __syncthreads();

    int row = tid & 127, half = tid >> 7;
    if (p == 1) {
        #pragma unroll
        for (int c = 0; c < 64; c++) {
            int col = half * 64 + c;
            float v = Csm[row * LDS2 + col] + bias[col];
            __nv_bfloat16 hi = __float2bfloat16_rn(v);
            size_t off = ((size_t)(h * D + col)) * N_TOK + n0 + row;
            g_kT_hi[off] = hi;
            g_kT_lo[off] = __float2bfloat16_rn(v - __bfloat162float(hi));
        }
    } else {
        __nv_bfloat16* oh = ((p == 0) ? g_q_hi : g_v_hi) +
                            ((size_t)h * N_TOK + n0 + row) * D + half * 64;
        __nv_bfloat16* ol = ((p == 0) ? g_q_lo : g_v_lo) +
                            ((size_t)h * N_TOK + n0 + row) * D + half * 64;
        #pragma unroll
        for (int g = 0; g < 8; g++) {
            uint32_t hw[4], lw[4];
            #pragma unroll
            for (int q = 0; q < 4; q++) {
                int col = half * 64 + g * 8 + 2 * q;
                float a  = Csm[row * LDS2 + col]     + bias[col];
                float d2 = Csm[row * LDS2 + col + 1] + bias[col + 1];
                float la, lb;
                hw[q] = pack_hi(a, d2, la, lb);
                lw[q] = pack2(la, lb);
            }
            ((uint4*)oh)[g] = make_uint4(hw[0], hw[1], hw[2], hw[3]);
            ((uint4*)ol)[g] = make_uint4(lw[0], lw[1], lw[2], lw[3]);
        }
    }
}

// ===========================================================================
// Kernel B: flash attention, raw mma.sync + register softmax.
// grid (32, H), block 256 (8 warps).  Warp w owns rows w*16..w*16+15.
// V held in registers; Q/K chunks (64 wide) double-buffered via cp.async.
// ===========================================================================
__global__ void __launch_bounds__(256, 1) attn_tc_kernel() {
    extern __shared__ char sm[];
    uint32_t smb = smem_u32(sm);
    int tid = threadIdx.x, wid = tid >> 5, lane = tid & 31;
    int h = blockIdx.y, n0 = blockIdx.x * 128;
    int g = lane >> 2, t4 = lane & 3;
    int r0 = wid * 16;

    const __nv_bfloat16* qb_hi = g_q_hi + (size_t)h * N_TOK * D;
    const __nv_bfloat16* qb_lo = g_q_lo + (size_t)h * N_TOK * D;
    const __nv_bfloat16* kb_hi = g_kT_hi + (size_t)h * D * N_TOK;
    const __nv_bfloat16* kb_lo = g_kT_lo + (size_t)h * D * N_TOK;

    // ldmatrix lane-address components (same pattern for V/Q/K)
    int lrow = (lane & 7) + ((lane & 8) ? 8 : 0);    // for A-style (V): row sel
    // For A frags (V): lanes 0-7 rows+0 klo; 8-15 rows+8 klo; 16-23 rows+0 khi; 24-31 rows+8 khi
    int a_row = (lane & 7) + ((lane & 8) ? 8 : 0);
    int a_kof = (lane & 16) ? 8 : 0;
    // For B frags (Q/K): lanes 0-7 rows+0 klo; 8-15 rows+0 khi; 16-23 rows+8 klo; 24-31 rows+8 khi
    int b_row = (lane & 7) + ((lane & 16) ? 8 : 0);
    int b_kof = (lane & 8) ? 8 : 0;
    (void)lrow;

    // ---- stage V and load fragments (hi then lo), using Qbuf0 region ----
    uint32_t Vh[8][4], Vl[8][4];
    {
        __nv_bfloat16* Vst = (__nv_bfloat16*)sm;       // [128][136]
        const __nv_bfloat16* vsrc = g_v_hi + ((size_t)h * N_TOK + n0) * D;
        #pragma unroll
        for (int it = 0; it < 8; it++) {
            int idx = tid + it * 256;
            int row = idx >> 4, c16 = idx & 15;
            *(uint4*)(Vst + row * LDQ + c16 * 8) =
                *(const uint4*)(vsrc + (size_t)row * D + c16 * 8);
        }
        __syncthreads();
        #pragma unroll
        for (int kt = 0; kt < 8; kt++) {
            uint32_t ad = smb + ((r0 + a_row) * LDQ + kt * 16 + a_kof) * 2;
            LDMX4(Vh[kt], ad);
        }
        __syncthreads();
        vsrc = g_v_lo + ((size_t)h * N_TOK + n0) * D;
        #pragma unroll
        for (int it = 0; it < 8; it++) {
            int idx = tid + it * 256;
            int row = idx >> 4, c16 = idx & 15;
            *(uint4*)(Vst + row * LDQ + c16 * 8) =
                *(const uint4*)(vsrc + (size_t)row * D + c16 * 8);
        }
        __syncthreads();
        #pragma unroll
        for (int kt = 0; kt < 8; kt++) {
            uint32_t ad = smb + ((r0 + a_row) * LDQ + kt * 16 + a_kof) * 2;
            LDMX4(Vl[kt], ad);
        }
        __syncthreads();
    }

    // ---- prefetch chunk 0 into buf 0 ----
    {
        #pragma unroll
        for (int it = 0; it < 4; it++) {
            int idx = tid + it * 256;
            int row = idx >> 4, c16 = idx & 15;
            uint32_t dof = (uint32_t)(row * LDQ + c16 * 8) * 2;
            cp_async16_u(smb + AQ0 + dof, qb_hi + (size_t)row * D + c16 * 8);
            cp_async16_u(smb + AQ0 + QPL + dof, qb_lo + (size_t)row * D + c16 * 8);
        }
        #pragma unroll
        for (int it = 0; it < 4; it++) {
            int idx = tid + it * 256;
            int row = idx >> 3, c16 = idx & 7;
            uint32_t dof = (uint32_t)(row * LDKT + c16 * 8) * 2;
            cp_async16_u(smb + AK0 + dof, kb_hi + (size_t)row * N_TOK + c16 * 8);
            cp_async16_u(smb + AK0 + KPL + dof, kb_lo + (size_t)row * N_TOK + c16 * 8);
        }
        CP_COMMIT();
    }

    float o[16][4];
    #pragma unroll
    for (int j = 0; j < 16; j++)
        #pragma unroll
        for (int e = 0; e < 4; e++) o[j][e] = 0.f;
    float m_a = -INFINITY, m_b = -INFINITY, l_a = 0.f, l_b = 0.f;

    for (int jt = 0; jt < NC; jt++) {
        CP_WAIT0();
        __syncthreads();

        uint32_t qbase = smb + ((jt & 1) ? AQ1 : AQ0);
        uint32_t kbase = smb + ((jt & 1) ? AK1 : AK0);

        // prefetch next chunk into other buffers (overlaps compute)
        if (jt + 1 < NC) {
            uint32_t qn = smb + ((jt & 1) ? AQ0 : AQ1);
            uint32_t kn = smb + ((jt & 1) ? AK0 : AK1);
            const __nv_bfloat16* qs_hi = qb_hi + (size_t)(jt + 1) * 64 * D;
            const __nv_bfloat16* qs_lo = qb_lo + (size_t)(jt + 1) * 64 * D;
            const __nv_bfloat16* ks_hi = kb_hi + (size_t)(jt + 1) * 64;
            const __nv_bfloat16* ks_lo = kb_lo + (size_t)(jt + 1) * 64;
            #pragma unroll
            for (int it = 0; it < 4; it++) {
                int idx = tid + it * 256;
                int row = idx >> 4, c16 = idx & 15;
                uint32_t dof = (uint32_t)(row * LDQ + c16 * 8) * 2;
                cp_async16_u(qn + dof, qs_hi + (size_t)row * D + c16 * 8);
                cp_async16_u(qn + QPL + dof, qs_lo + (size_t)row * D + c16 * 8);
            }
            #pragma unroll
            for (int it = 0; it < 4; it++) {
                int idx = tid + it * 256;
                int row = idx >> 3, c16 = idx & 7;
                uint32_t dof = (uint32_t)(row * LDKT + c16 * 8) * 2;
                cp_async16_u(kn + dof, ks_hi + (size_t)row * N_TOK + c16 * 8);
                cp_async16_u(kn + KPL + dof, ks_lo + (size_t)row * N_TOK + c16 * 8);
            }
            CP_COMMIT();
        }

        // ---- GEMM1: S[16x64] = V(rows r0..r0+15) @ Qchunk^T ----
        float s[8][4];
        #pragma unroll
        for (int j = 0; j < 8; j++)
            #pragma unroll
            for (int e = 0; e < 4; e++) s[j][e] = 0.f;

        #pragma unroll
        for (int kt = 0; kt < 8; kt++) {
            #pragma unroll
            for (int p = 0; p < 4; p++) {
                uint32_t bh[4], bl[4];
                uint32_t ad = qbase + ((16 * p + b_row) * LDQ + kt * 16 + b_kof) * 2;
                LDMX4(bh, ad);
                LDMX4(bl, ad + QPL);
                MMA16816(s[2 * p],     Vh[kt], bh[0], bh[1]);
                MMA16816(s[2 * p],     Vh[kt], bl[0], bl[1]);
                MMA16816(s[2 * p],     Vl[kt], bh[0], bh[1]);
                MMA16816(s[2 * p + 1], Vh[kt], bh[2], bh[3]);
                MMA16816(s[2 * p + 1], Vh[kt], bl[2], bl[3]);
                MMA16816(s[2 * p + 1], Vl[kt], bh[2], bh[3]);
            }
        }

        // ---- register softmax (rows r0+g and r0+g+8, warp-local) ----
        float ma = -INFINITY, mb = -INFINITY;
        #pragma unroll
        for (int j = 0; j < 8; j++) {
            ma = fmaxf(ma, fmaxf(s[j][0], s[j][1]));
            mb = fmaxf(mb, fmaxf(s[j][2], s[j][3]));
        }
        ma = fmaxf(ma, __shfl_xor_sync(0xffffffffu, ma, 1));
        ma = fmaxf(ma, __shfl_xor_sync(0xffffffffu, ma, 2));
        mb = fmaxf(mb, __shfl_xor_sync(0xffffffffu, mb, 1));
        mb = fmaxf(mb, __shfl_xor_sync(0xffffffffu, mb, 2));
        float mna = fmaxf(m_a, ma), mnb = fmaxf(m_b, mb);
        float fa = __expf(m_a - mna), fb = __expf(m_b - mnb);
        float la = 0.f, lb = 0.f;
        #pragma unroll
        for (int j = 0; j < 8; j++) {
            s[j][0] = __expf(s[j][0] - mna);
            s[j][1] = __expf(s[j][1] - mna);
            s[j][2] = __expf(s[j][2] - mnb);
            s[j][3] = __expf(s[j][3] - mnb);
            la += s[j][0] + s[j][1];
            lb += s[j][2] + s[j][3];
        }
        la += __shfl_xor_sync(0xffffffffu, la, 1);
        la += __shfl_xor_sync(0xffffffffu, la, 2);
        lb += __shfl_xor_sync(0xffffffffu, lb, 1);
        lb += __shfl_xor_sync(0xffffffffu, lb, 2);
        l_a = l_a * fa + la;
        l_b = l_b * fb + lb;
        m_a = mna; m_b = mnb;

        // rescale O
        #pragma unroll
        for (int j = 0; j < 16; j++) {
            o[j][0] *= fa; o[j][1] *= fa;
            o[j][2] *= fb; o[j][3] *= fb;
        }

        // ---- repack P (accumulator -> A fragments), hi/lo split ----
        uint32_t Ph[4][4], Pl[4][4];
        #pragma unroll
        for (int kt2 = 0; kt2 < 4; kt2++) {
            int j0 = 2 * kt2, j1 = 2 * kt2 + 1;
            float l0, l1;
            Ph[kt2][0] = pack_hi(s[j0][0], s[j0][1], l0, l1); Pl[kt2][0] = pack2(l0, l1);
            Ph[kt2][1] = pack_hi(s[j0][2], s[j0][3], l0, l1); Pl[kt2][1] = pack2(l0, l1);
            Ph[kt2][2] = pack_hi(s[j1][0], s[j1][1], l0, l1); Pl[kt2][2] = pack2(l0, l1);
            Ph[kt2][3] = pack_hi(s[j1][2], s[j1][3], l0, l1); Pl[kt2][3] = pack2(l0, l1);
        }

        // ---- GEMM2: O[16x128] += P @ Kchunk ----
        #pragma unroll
        for (int kt2 = 0; kt2 < 4; kt2++) {
            #pragma unroll
            for (int p = 0; p < 8; p++) {
                uint32_t bh[4], bl[4];
                uint32_t ad = kbase + ((16 * p + b_row) * LDKT + kt2 * 16 + b_kof) * 2;
                LDMX4(bh, ad);
                LDMX4(bl, ad + KPL);
                MMA16816(o[2 * p],     Ph[kt2], bh[0], bh[1]);
                MMA16816(o[2 * p],     Ph[kt2], bl[0], bl[1]);
                MMA16816(o[2 * p],     Pl[kt2], bh[0], bh[1]);
                MMA16816(o[2 * p + 1], Ph[kt2], bh[2], bh[3]);
                MMA16816(o[2 * p + 1], Ph[kt2], bl[2], bl[3]);
                MMA16816(o[2 * p + 1], Pl[kt2], bh[2], bh[3]);
            }
        }
    }

    // ---- epilogue: normalize, split hi/lo, store to g_att ----
    {
        float ia = 1.f / l_a, ib = 1.f / l_b;
        int rowa = n0 + r0 + g, rowb = rowa + 8;
        __nv_bfloat16* oha = g_att_hi + (size_t)rowa * (H * D) + h * D;
        __nv_bfloat16* ola = g_att_lo + (size_t)rowa * (H * D) + h * D;
        __nv_bfloat16* ohb = g_att_hi + (size_t)rowb * (H * D) + h * D;
        __nv_bfloat16* olb = g_att_lo + (size_t)rowb * (H * D) + h * D;
        #pragma unroll
        for (int j = 0; j < 16; j++) {
            int col = 8 * j + 2 * t4;
            float l0, l1;
            uint32_t hh = pack_hi(o[j][0] * ia, o[j][1] * ia, l0, l1);
            *(uint32_t*)(oha + col) = hh;
            *(uint32_t*)(ola + col) = pack2(l0, l1);
            hh = pack_hi(o[j][2] * ib, o[j][3] * ib, l0, l1);
            *(uint32_t*)(ohb + col) = hh;
            *(uint32_t*)(olb + col) = pack2(l0, l1);
        }
    }
}

// ===========================================================================
// Kernel C: out[n][f] = att[n][:1024] @ WoT^T + bo.  grid 64 (64-row tiles).
// ===========================================================================
__global__ void __launch_bounds__(256, 1)
oproj_tc_kernel(const float* __restrict__ bo, float* __restrict__ out) {
    extern __shared__ char sm[];
    __nv_bfloat16* Ahi = (__nv_bfloat16*)(sm + OP_A);
    __nv_bfloat16* Alo = Ahi + 64 * LDB;
    __nv_bfloat16* Bhi = (__nv_bfloat16*)(sm + OP_B);
    __nv_bfloat16* Blo = Bhi + 128 * LDB;
    float* Csm = (float*)(sm + OP_C);
    float* bias = (float*)(sm + OFF_BIAS);

    int tid = threadIdx.x, wid = tid >> 5;
    int n0 = blockIdx.x * 64;
    int r0 = (wid & 1) * 32, c0 = (wid >> 1) * 32;
    if (tid < 128) bias[tid] = bo[tid];

    FragC acc[2][2];
    #pragma unroll
    for (int i = 0; i < 2; i++)
        #pragma unroll
        for (int j = 0; j < 2; j++) wmma::fill_fragment(acc[i][j], 0.f);

    for (int kt = 0; kt < 8; kt++) {
        ld_tile64(g_att_hi + (size_t)n0 * (H * D) + kt * 128, H * D, Ahi);
        ld_tile64(g_att_lo + (size_t)n0 * (H * D) + kt * 128, H * D, Alo);
        ld_tile(g_WoT_hi + kt * 128, H * D, Bhi);
        ld_tile(g_WoT_lo + kt * 128, H * D, Blo);
        __syncthreads();
        gemm3_22(acc, Ahi, Alo, Bhi, Blo, r0, c0);
        __syncthreads();
    }

    #pragma unroll
    for (int i = 0; i < 2; i++)
        #pragma unroll
        for (int j = 0; j < 2; j++)
            wmma::store_matrix_sync(&Csm[(r0 + 16 * i) * LDS2 + c0 + 16 * j],
                                    acc[i][j], LDS2, wmma::mem_row_major);
    __syncthreads();

    int row = tid >> 2, cq = tid & 3;
    float* op = out + (size_t)(n0 + row) * D + cq * 32;
    #pragma unroll
    for (int q4 = 0; q4 < 8; q4++) {
        int col = cq * 32 + q4 * 4;
        float4 v4 = *(const float4*)&Csm[row * LDS2 + col];
        v4.x += bias[col];     v4.y += bias[col + 1];
        v4.z += bias[col + 2]; v4.w += bias[col + 3];
        ((float4*)op)[q4] = v4;
    }
}

// ===========================================================================
extern "C" void kernel_launch(void* const* d_in, const int* in_sizes, int n_in,
                              void* d_out, int out_size) {
    const float* x  = (const float*)d_in[0];
    const float* Wq = (const float*)d_in[1];
    const float* bq = (const float*)d_in[2];
    const float* Wk = (const float*)d_in[3];
    const float* bk = (const float*)d_in[4];
    const float* Wv = (const float*)d_in[5];
    const float* bv = (const float*)d_in[6];
    const float* Wo = (const float*)d_in[7];
    const float* bo = (const float*)d_in[8];
    float* out = (float*)d_out;

    cudaFuncSetAttribute(qkv_tc_kernel,   cudaFuncAttributeMaxDynamicSharedMemorySize, SM_QKV);
    cudaFuncSetAttribute(attn_tc_kernel,  cudaFuncAttributeMaxDynamicSharedMemorySize, SM_ATTN);
    cudaFuncSetAttribute(oproj_tc_kernel, cudaFuncAttributeMaxDynamicSharedMemorySize, SM_OPROJ);

    prep_kernel<<<256, 256>>>(x, Wq, Wk, Wv, Wo);
    qkv_tc_kernel<<<dim3(32, 24), 256, SM_QKV>>>(bq, bk, bv);
    attn_tc_kernel<<<dim3(32, H), 256, SM_ATTN>>>();
    oproj_tc_kernel<<<64, 256, SM_OPROJ>>>(bo, out);
}